// round 10
// baseline (speedup 1.0000x reference)
#include <cuda_runtime.h>
#include <cuda_bf16.h>
#include <math.h>

#define HH 96
#define WWD 96
#define NPIX (HH*WWD)
#define BATCH 2
#define CCH 64
#define INNER 3
#define BM 64
#define BN 64
#define NITER (NPIX/BN)
#define SKH 72

__device__ float g_xred[BATCH*INNER*NPIX];
__device__ __nv_bfloat16 g_tok[(size_t)BATCH*NPIX*CCH];    /* raw tokens (K/V) */
__device__ __nv_bfloat16 g_tokq[(size_t)BATCH*NPIX*CCH];   /* tokens * SC (Q)  */

/* ------------------------------------------------------------------ */
/* helpers                                                             */
/* ------------------------------------------------------------------ */
__device__ __forceinline__ float ex2f(float v) {
    float r;
    asm("ex2.approx.ftz.f32 %0, %1;" : "=f"(r) : "f"(v));
    return r;
}

__device__ __forceinline__ unsigned packbf(float a, float b) {
    __nv_bfloat162 h = __floats2bfloat162_rn(a, b);
    return *reinterpret_cast<unsigned*>(&h);
}

__device__ __forceinline__ void ldsm4(unsigned* r, unsigned a) {
    asm volatile(
        "ldmatrix.sync.aligned.m8n8.x4.shared.b16 {%0,%1,%2,%3}, [%4];"
        : "=r"(r[0]), "=r"(r[1]), "=r"(r[2]), "=r"(r[3])
        : "r"(a));
}

__device__ __forceinline__ void ldsm4t(unsigned* r, unsigned a) {
    asm volatile(
        "ldmatrix.sync.aligned.m8n8.x4.trans.shared.b16 {%0,%1,%2,%3}, [%4];"
        : "=r"(r[0]), "=r"(r[1]), "=r"(r[2]), "=r"(r[3])
        : "r"(a));
}

__device__ __forceinline__ void mma16816(float* d, const unsigned* a,
                                         const unsigned* b) {
    asm volatile(
        "mma.sync.aligned.m16n8k16.row.col.f32.bf16.bf16.f32 "
        "{%0,%1,%2,%3}, {%4,%5,%6,%7}, {%8,%9}, {%0,%1,%2,%3};"
        : "+f"(d[0]), "+f"(d[1]), "+f"(d[2]), "+f"(d[3])
        : "r"(a[0]), "r"(a[1]), "r"(a[2]), "r"(a[3]), "r"(b[0]), "r"(b[1]));
}

__device__ __forceinline__ void cpasync16(unsigned dst, const void* src) {
    asm volatile("cp.async.cg.shared.global [%0], [%1], 16;"
                 :: "r"(dst), "l"(src) : "memory");
}

/* ------------------------------------------------------------------ */
/* Kernel A: 1x1 reduce conv 64 -> 3                                   */
/* ------------------------------------------------------------------ */
__global__ void kred(const float* __restrict__ x,
                     const float* __restrict__ w_red,
                     const float* __restrict__ b_red) {
    __shared__ float ws[INNER*CCH];
    __shared__ float bs[INNER];
    for (int i = threadIdx.x; i < INNER*CCH; i += blockDim.x) { ws[i] = w_red[i]; }
    if (threadIdx.x < INNER) { bs[threadIdx.x] = b_red[threadIdx.x]; }
    __syncthreads();
    int p = blockIdx.x*blockDim.x + threadIdx.x;
    if (p >= BATCH*NPIX) { return; }
    int b = p / NPIX;
    int n = p % NPIX;
    float a0 = bs[0];
    float a1 = bs[1];
    float a2 = bs[2];
    const float* xp = x + (size_t)b*CCH*NPIX + n;
    #pragma unroll 16
    for (int c = 0; c < CCH; c++) {
        float xv = xp[(size_t)c*NPIX];
        a0 += ws[0*CCH+c]*xv;
        a1 += ws[1*CCH+c]*xv;
        a2 += ws[2*CCH+c]*xv;
    }
    g_xred[(b*INNER+0)*NPIX + n] = a0;
    g_xred[(b*INNER+1)*NPIX + n] = a1;
    g_xred[(b*INNER+2)*NPIX + n] = a2;
}

/* ------------------------------------------------------------------ */
/* Kernel B: dilated convs + C4 products + 1x1 fuse -> bf16 tokens     */
/* Writes raw tokens (g_tok) and SC-scaled tokens (g_tokq).            */
/* ------------------------------------------------------------------ */
__global__ void kfuse(const float* __restrict__ w_dil,
                      const float* __restrict__ b_dil,
                      const float* __restrict__ w_fuse,
                      const float* __restrict__ b_fuse) {
    __shared__ float wf[CCH*54];
    __shared__ float wd[243];
    __shared__ float bd[9];
    __shared__ float bf[CCH];
    for (int i = threadIdx.x; i < CCH*54; i += blockDim.x) { wf[i] = w_fuse[i]; }
    for (int i = threadIdx.x; i < 243;    i += blockDim.x) { wd[i] = w_dil[i]; }
    if (threadIdx.x < 9)   { bd[threadIdx.x] = b_dil[threadIdx.x]; }
    if (threadIdx.x < CCH) { bf[threadIdx.x] = b_fuse[threadIdx.x]; }
    __syncthreads();

    int p = blockIdx.x*blockDim.x + threadIdx.x;
    if (p >= BATCH*NPIX) { return; }
    int b = p / NPIX;
    int n = p % NPIX;
    int h = n / WWD;
    int w = n % WWD;
    const float* xr = g_xred + (size_t)b*INNER*NPIX;

    float co[3][3];
    #pragma unroll
    for (int i = 0; i < 3; i++) {
        int d = i + 1;
        float a0 = bd[i*3+0];
        float a1 = bd[i*3+1];
        float a2 = bd[i*3+2];
        #pragma unroll
        for (int kh = 0; kh < 3; kh++) {
            int hh = h + (kh-1)*d;
            if (hh < 0 || hh >= HH) { continue; }
            #pragma unroll
            for (int kw = 0; kw < 3; kw++) {
                int ww = w + (kw-1)*d;
                if (ww < 0 || ww >= WWD) { continue; }
                int off = hh*WWD + ww;
                #pragma unroll
                for (int cj = 0; cj < 3; cj++) {
                    float xv = xr[cj*NPIX + off];
                    int wb = (i*3)*27 + cj*9 + kh*3 + kw;
                    a0 += wd[wb +  0]*xv;
                    a1 += wd[wb + 27]*xv;
                    a2 += wd[wb + 54]*xv;
                }
            }
        }
        co[i][0] = a0;
        co[i][1] = a1;
        co[i][2] = a2;
    }

    int hc[6];
    int wc[6];
    hc[0] = h;        wc[0] = w;
    hc[1] = h;        wc[1] = WWD-1-w;
    hc[2] = HH-1-h;   wc[2] = w;
    hc[3] = w;        wc[3] = HH-1-h;
    hc[4] = HH-1-h;   wc[4] = WWD-1-w;
    hc[5] = WWD-1-w;  wc[5] = h;

    float g[54];
    #pragma unroll
    for (int t = 0; t < 6; t++) {
        int off = hc[t]*WWD + wc[t];
        float t0 = xr[0*NPIX+off];
        float t1 = xr[1*NPIX+off];
        float t2 = xr[2*NPIX+off];
        #pragma unroll
        for (int i = 0; i < 3; i++) {
            int base = (i*6 + t)*3;
            g[base+0] = co[i][0]*t0;
            g[base+1] = co[i][1]*t1;
            g[base+2] = co[i][2]*t2;
        }
    }

    const float SC = 0.18033688011112042f;  /* 0.125 * log2(e) */
    __nv_bfloat16* tok  = g_tok  + ((size_t)b*NPIX + n)*CCH;
    __nv_bfloat16* tokq = g_tokq + ((size_t)b*NPIX + n)*CCH;
    #pragma unroll 4
    for (int c4 = 0; c4 < CCH; c4 += 4) {
        float a[4];
        #pragma unroll
        for (int u = 0; u < 4; u++) {
            float acc = bf[c4+u];
            const float* wr = &wf[(c4+u)*54];
            #pragma unroll
            for (int j = 0; j < 54; j++) { acc += wr[j]*g[j]; }
            a[u] = acc;
        }
        uint2 wv;
        wv.x = packbf(a[0], a[1]);
        wv.y = packbf(a[2], a[3]);
        *reinterpret_cast<uint2*>(&tok[c4]) = wv;
        uint2 wq;
        wq.x = packbf(a[0]*SC, a[1]*SC);
        wq.y = packbf(a[2]*SC, a[3]*SC);
        *reinterpret_cast<uint2*>(&tokq[c4]) = wq;
    }
}

/* ------------------------------------------------------------------ */
/* Kernel C: bf16 flash attention, mma.sync.m16n8k16, warp-split-N.    */
/* 8 warps / 256 threads, BM=64 rows. Warp w: row block (w&3)*16,      */
/* score-column half (w>>2)*32. Each warp keeps partial O and partial  */
/* row sum over its token half; partner warps (w, w+4) reduce via      */
/* smem once at the end. No running max (bounded scores), Q            */
/* pre-scaled, row sums via tensor-core ones-MMA.                      */
/* ------------------------------------------------------------------ */
__global__ __launch_bounds__(256, 2)
void kattn(const float* __restrict__ x, float* __restrict__ out) {
    __shared__ __nv_bfloat16 KV[2][BN*SKH];   /* 18432 B, reused as scratch */

    const int tid  = threadIdx.x;
    const int lane = tid & 31;
    const int wid  = tid >> 5;
    const int wr   = wid & 3;       /* row block   */
    const int hN   = wid >> 2;      /* column half */
    const int b    = blockIdx.y;
    const int n0   = blockIdx.x * BM;
    const int grp  = lane >> 3;
    const int gi   = lane & 7;
    const __nv_bfloat16* tok = g_tok + (size_t)b*NPIX*CCH;

    const unsigned kv0 = (unsigned)__cvta_generic_to_shared(&KV[0][0]);

    /* all-ones bf16 B fragment for row-sum MMAs */
    unsigned ones2[2];
    ones2[0] = 0x3F803F80u;
    ones2[1] = 0x3F803F80u;

    /* Q fragments from the pre-scaled token array */
    unsigned qa[4][4];
    {
        const __nv_bfloat16* tq = g_tokq + (size_t)b*NPIX*CCH;
        int g0 = n0 + wr*16 + (lane >> 2);
        int kk = (lane & 3)*2;
        const __nv_bfloat16* q0 = tq + (size_t)g0*CCH;
        const __nv_bfloat16* q8 = tq + (size_t)(g0+8)*CCH;
        #pragma unroll
        for (int ks = 0; ks < 4; ks++) {
            qa[ks][0] = *reinterpret_cast<const unsigned*>(q0 + 16*ks + kk);
            qa[ks][1] = *reinterpret_cast<const unsigned*>(q8 + 16*ks + kk);
            qa[ks][2] = *reinterpret_cast<const unsigned*>(q0 + 16*ks + kk + 8);
            qa[ks][3] = *reinterpret_cast<const unsigned*>(q8 + 16*ks + kk + 8);
        }
    }

    float oc[8][4];   /* partial O over this warp's token half */
    #pragma unroll
    for (int i = 0; i < 8; i++) {
        #pragma unroll
        for (int j = 0; j < 4; j++) { oc[i][j] = 0.0f; }
    }
    float lacc[4];
    lacc[0] = 0.0f; lacc[1] = 0.0f; lacc[2] = 0.0f; lacc[3] = 0.0f;

    /* prefetch tile 0: 512 16B chunks, 256 threads x 2 */
    {
        #pragma unroll
        for (int u = 0; u < 2; u++) {
            int chunk = tid + u*256;
            int r  = chunk >> 3;
            int cg = (chunk & 7)*8;
            cpasync16(kv0 + (unsigned)(r*SKH + cg)*2u, tok + (size_t)r*CCH + cg);
        }
        asm volatile("cp.async.commit_group;" ::: "memory");
    }

    for (int t = 0; t < NITER; t++) {
        const int cur = t & 1;
        const unsigned kvb = kv0 + (unsigned)cur*(BN*SKH*2u);

        asm volatile("cp.async.wait_group 0;" ::: "memory");
        __syncthreads();

        if (t + 1 < NITER) {
            unsigned dst0 = kv0 + (unsigned)(cur ^ 1)*(BN*SKH*2u);
            #pragma unroll
            for (int u = 0; u < 2; u++) {
                int chunk = tid + u*256;
                int r  = chunk >> 3;
                int cg = (chunk & 7)*8;
                cpasync16(dst0 + (unsigned)(r*SKH + cg)*2u,
                          tok + (size_t)((t+1)*BN + r)*CCH + cg);
            }
            asm volatile("cp.async.commit_group;" ::: "memory");
        }

        /* GEMM1: sc = (Q*SC) * K^T over this warp's 32 columns */
        float sc[4][4];
        #pragma unroll
        for (int i = 0; i < 4; i++) {
            #pragma unroll
            for (int j = 0; j < 4; j++) { sc[i][j] = 0.0f; }
        }

        #pragma unroll
        for (int np = 0; np < 2; np++) {
            #pragma unroll
            for (int ks = 0; ks < 4; ks++) {
                int n_row = hN*32 + (2*np + (grp >> 1))*8 + gi;
                int k_off = 16*ks + (grp & 1)*8;
                unsigned r[4];
                ldsm4(r, kvb + (unsigned)(n_row*SKH + k_off)*2u);
                mma16816(sc[2*np+0], qa[ks], &r[0]);
                mma16816(sc[2*np+1], qa[ks], &r[2]);
            }
        }

        /* P = exp2(sc) */
        #pragma unroll
        for (int nt = 0; nt < 4; nt++) {
            sc[nt][0] = ex2f(sc[nt][0]);
            sc[nt][1] = ex2f(sc[nt][1]);
            sc[nt][2] = ex2f(sc[nt][2]);
            sc[nt][3] = ex2f(sc[nt][3]);
        }

        /* repack P C-frags (16x32) into 2 bf16 A k-groups */
        unsigned pa[2][4];
        #pragma unroll
        for (int j = 0; j < 2; j++) {
            pa[j][0] = packbf(sc[2*j+0][0], sc[2*j+0][1]);
            pa[j][1] = packbf(sc[2*j+0][2], sc[2*j+0][3]);
            pa[j][2] = packbf(sc[2*j+1][0], sc[2*j+1][1]);
            pa[j][3] = packbf(sc[2*j+1][2], sc[2*j+1][3]);
        }

        /* partial row sums via tensor core */
        #pragma unroll
        for (int j = 0; j < 2; j++) {
            mma16816(lacc, pa[j], ones2);
        }

        /* GEMM2: O += P * V over this warp's 32 token rows */
        #pragma unroll
        for (int np = 0; np < 4; np++) {
            #pragma unroll
            for (int ks = 0; ks < 2; ks++) {
                int tokr = hN*32 + 16*ks + (grp & 1)*8 + gi;
                int ch   = (2*np + (grp >> 1))*8;
                unsigned r[4];
                ldsm4t(r, kvb + (unsigned)(tokr*SKH + ch)*2u);
                mma16816(oc[2*np+0], pa[ks], &r[0]);
                mma16816(oc[2*np+1], pa[ks], &r[2]);
            }
        }
    }

    /* combine partner-warp partials (w and w+4) via smem scratch.     */
    /* KV buffer is done being read; reuse it: 4 blocks x 32 lanes x   */
    /* 36 floats = 18432 B exactly.                                    */
    float* scratch = reinterpret_cast<float*>(&KV[0][0]);
    __syncthreads();
    if (wid >= 4) {
        float* s = scratch + (wr*32 + lane)*36;
        #pragma unroll
        for (int nt = 0; nt < 8; nt++) {
            #pragma unroll
            for (int j = 0; j < 4; j++) { s[nt*4 + j] = oc[nt][j]; }
        }
        s[32] = lacc[0];
        s[33] = lacc[2];
    }
    __syncthreads();
    if (wid < 4) {
        float* s = scratch + (wr*32 + lane)*36;
        #pragma unroll
        for (int nt = 0; nt < 8; nt++) {
            #pragma unroll
            for (int j = 0; j < 4; j++) { oc[nt][j] += s[nt*4 + j]; }
        }
        float inv0 = 1.0f / (lacc[0] + s[32]);
        float inv1 = 1.0f / (lacc[2] + s[33]);

        int r0g = n0 + wr*16 + (lane >> 2);
        #pragma unroll
        for (int nt = 0; nt < 8; nt++) {
            int ch = nt*8 + (lane & 3)*2;
            #pragma unroll
            for (int dv = 0; dv < 2; dv++) {
                size_t idx0 = ((size_t)b*CCH + ch + dv)*NPIX + r0g;
                out[idx0]     = x[idx0]     + 0.2f*oc[nt][dv]*inv0;
                out[idx0 + 8] = x[idx0 + 8] + 0.2f*oc[nt][2+dv]*inv1;
            }
        }
    }
}

/* ------------------------------------------------------------------ */
extern "C" void kernel_launch(void* const* d_in, const int* in_sizes, int n_in,
                              void* d_out, int out_size) {
    const float* x      = (const float*)d_in[0];
    const float* w_red  = (const float*)d_in[1];
    const float* b_red  = (const float*)d_in[2];
    const float* w_dil  = (const float*)d_in[3];
    const float* b_dil  = (const float*)d_in[4];
    const float* w_fuse = (const float*)d_in[5];
    const float* b_fuse = (const float*)d_in[6];
    float* out = (float*)d_out;

    int npx = BATCH*NPIX;
    kred<<<(npx+127)/128, 128>>>(x, w_red, b_red);
    kfuse<<<(npx+127)/128, 128>>>(w_dil, b_dil, w_fuse, b_fuse);

    dim3 grid(NPIX/BM, BATCH);
    kattn<<<grid, 256>>>(x, out);
}

// round 12
// speedup vs baseline: 1.0210x; 1.0210x over previous
#include <cuda_runtime.h>
#include <cuda_bf16.h>
#include <math.h>

#define HH 96
#define WWD 96
#define NPIX (HH*WWD)
#define BATCH 2
#define CCH 64
#define INNER 3
#define BM 64
#define BN 64
#define NITER (NPIX/BN)
#define SKH 72

__device__ float g_xred[BATCH*INNER*NPIX];
__device__ __nv_bfloat16 g_tok[(size_t)BATCH*NPIX*CCH];    /* raw tokens (K/V) */
__device__ __nv_bfloat16 g_tokq[(size_t)BATCH*NPIX*CCH];   /* tokens * SC (Q)  */

/* ------------------------------------------------------------------ */
/* helpers                                                             */
/* ------------------------------------------------------------------ */
__device__ __forceinline__ float ex2f(float v) {
    float r;
    asm("ex2.approx.ftz.f32 %0, %1;" : "=f"(r) : "f"(v));
    return r;
}

__device__ __forceinline__ unsigned packbf(float a, float b) {
    __nv_bfloat162 h = __floats2bfloat162_rn(a, b);
    return *reinterpret_cast<unsigned*>(&h);
}

__device__ __forceinline__ void ldsm4(unsigned* r, unsigned a) {
    asm volatile(
        "ldmatrix.sync.aligned.m8n8.x4.shared.b16 {%0,%1,%2,%3}, [%4];"
        : "=r"(r[0]), "=r"(r[1]), "=r"(r[2]), "=r"(r[3])
        : "r"(a));
}

__device__ __forceinline__ void ldsm4t(unsigned* r, unsigned a) {
    asm volatile(
        "ldmatrix.sync.aligned.m8n8.x4.trans.shared.b16 {%0,%1,%2,%3}, [%4];"
        : "=r"(r[0]), "=r"(r[1]), "=r"(r[2]), "=r"(r[3])
        : "r"(a));
}

__device__ __forceinline__ void mma16816(float* d, const unsigned* a,
                                         const unsigned* b) {
    asm volatile(
        "mma.sync.aligned.m16n8k16.row.col.f32.bf16.bf16.f32 "
        "{%0,%1,%2,%3}, {%4,%5,%6,%7}, {%8,%9}, {%0,%1,%2,%3};"
        : "+f"(d[0]), "+f"(d[1]), "+f"(d[2]), "+f"(d[3])
        : "r"(a[0]), "r"(a[1]), "r"(a[2]), "r"(a[3]), "r"(b[0]), "r"(b[1]));
}

__device__ __forceinline__ void cpasync16(unsigned dst, const void* src) {
    asm volatile("cp.async.cg.shared.global [%0], [%1], 16;"
                 :: "r"(dst), "l"(src) : "memory");
}

/* ------------------------------------------------------------------ */
/* Kernel A: 1x1 reduce conv 64 -> 3                                   */
/* ------------------------------------------------------------------ */
__global__ void kred(const float* __restrict__ x,
                     const float* __restrict__ w_red,
                     const float* __restrict__ b_red) {
    __shared__ float ws[INNER*CCH];
    __shared__ float bs[INNER];
    for (int i = threadIdx.x; i < INNER*CCH; i += blockDim.x) { ws[i] = w_red[i]; }
    if (threadIdx.x < INNER) { bs[threadIdx.x] = b_red[threadIdx.x]; }
    __syncthreads();
    int p = blockIdx.x*blockDim.x + threadIdx.x;
    if (p >= BATCH*NPIX) { return; }
    int b = p / NPIX;
    int n = p % NPIX;
    float a0 = bs[0];
    float a1 = bs[1];
    float a2 = bs[2];
    const float* xp = x + (size_t)b*CCH*NPIX + n;
    #pragma unroll 16
    for (int c = 0; c < CCH; c++) {
        float xv = xp[(size_t)c*NPIX];
        a0 += ws[0*CCH+c]*xv;
        a1 += ws[1*CCH+c]*xv;
        a2 += ws[2*CCH+c]*xv;
    }
    g_xred[(b*INNER+0)*NPIX + n] = a0;
    g_xred[(b*INNER+1)*NPIX + n] = a1;
    g_xred[(b*INNER+2)*NPIX + n] = a2;
}

/* ------------------------------------------------------------------ */
/* Kernel B: dilated convs + C4 products + 1x1 fuse -> bf16 tokens     */
/* Writes raw tokens (g_tok) and SC-scaled tokens (g_tokq).            */
/* ------------------------------------------------------------------ */
__global__ void kfuse(const float* __restrict__ w_dil,
                      const float* __restrict__ b_dil,
                      const float* __restrict__ w_fuse,
                      const float* __restrict__ b_fuse) {
    __shared__ float wf[CCH*54];
    __shared__ float wd[243];
    __shared__ float bd[9];
    __shared__ float bf[CCH];
    for (int i = threadIdx.x; i < CCH*54; i += blockDim.x) { wf[i] = w_fuse[i]; }
    for (int i = threadIdx.x; i < 243;    i += blockDim.x) { wd[i] = w_dil[i]; }
    if (threadIdx.x < 9)   { bd[threadIdx.x] = b_dil[threadIdx.x]; }
    if (threadIdx.x < CCH) { bf[threadIdx.x] = b_fuse[threadIdx.x]; }
    __syncthreads();

    int p = blockIdx.x*blockDim.x + threadIdx.x;
    if (p >= BATCH*NPIX) { return; }
    int b = p / NPIX;
    int n = p % NPIX;
    int h = n / WWD;
    int w = n % WWD;
    const float* xr = g_xred + (size_t)b*INNER*NPIX;

    float co[3][3];
    #pragma unroll
    for (int i = 0; i < 3; i++) {
        int d = i + 1;
        float a0 = bd[i*3+0];
        float a1 = bd[i*3+1];
        float a2 = bd[i*3+2];
        #pragma unroll
        for (int kh = 0; kh < 3; kh++) {
            int hh = h + (kh-1)*d;
            if (hh < 0 || hh >= HH) { continue; }
            #pragma unroll
            for (int kw = 0; kw < 3; kw++) {
                int ww = w + (kw-1)*d;
                if (ww < 0 || ww >= WWD) { continue; }
                int off = hh*WWD + ww;
                #pragma unroll
                for (int cj = 0; cj < 3; cj++) {
                    float xv = xr[cj*NPIX + off];
                    int wb = (i*3)*27 + cj*9 + kh*3 + kw;
                    a0 += wd[wb +  0]*xv;
                    a1 += wd[wb + 27]*xv;
                    a2 += wd[wb + 54]*xv;
                }
            }
        }
        co[i][0] = a0;
        co[i][1] = a1;
        co[i][2] = a2;
    }

    int hc[6];
    int wc[6];
    hc[0] = h;        wc[0] = w;
    hc[1] = h;        wc[1] = WWD-1-w;
    hc[2] = HH-1-h;   wc[2] = w;
    hc[3] = w;        wc[3] = HH-1-h;
    hc[4] = HH-1-h;   wc[4] = WWD-1-w;
    hc[5] = WWD-1-w;  wc[5] = h;

    float g[54];
    #pragma unroll
    for (int t = 0; t < 6; t++) {
        int off = hc[t]*WWD + wc[t];
        float t0 = xr[0*NPIX+off];
        float t1 = xr[1*NPIX+off];
        float t2 = xr[2*NPIX+off];
        #pragma unroll
        for (int i = 0; i < 3; i++) {
            int base = (i*6 + t)*3;
            g[base+0] = co[i][0]*t0;
            g[base+1] = co[i][1]*t1;
            g[base+2] = co[i][2]*t2;
        }
    }

    const float SC = 0.18033688011112042f;  /* 0.125 * log2(e) */
    __nv_bfloat16* tok  = g_tok  + ((size_t)b*NPIX + n)*CCH;
    __nv_bfloat16* tokq = g_tokq + ((size_t)b*NPIX + n)*CCH;
    #pragma unroll 4
    for (int c4 = 0; c4 < CCH; c4 += 4) {
        float a[4];
        #pragma unroll
        for (int u = 0; u < 4; u++) {
            float acc = bf[c4+u];
            const float* wr = &wf[(c4+u)*54];
            #pragma unroll
            for (int j = 0; j < 54; j++) { acc += wr[j]*g[j]; }
            a[u] = acc;
        }
        uint2 wv;
        wv.x = packbf(a[0], a[1]);
        wv.y = packbf(a[2], a[3]);
        *reinterpret_cast<uint2*>(&tok[c4]) = wv;
        uint2 wq;
        wq.x = packbf(a[0]*SC, a[1]*SC);
        wq.y = packbf(a[2]*SC, a[3]*SC);
        *reinterpret_cast<uint2*>(&tokq[c4]) = wq;
    }
}

/* ------------------------------------------------------------------ */
/* Kernel C: bf16 flash attention, mma.sync.m16n8k16, warp-split-N.    */
/* 8 warps / 256 threads, BM=64 rows. Warp w: row block (w&3)*16,      */
/* score-column half (w>>2)*32. Each warp keeps partial O and partial  */
/* row sum over its token half; partner warps (w, w+4) reduce via      */
/* smem once at the end. No running max (bounded scores), Q            */
/* pre-scaled, row sums via tensor-core ones-MMA.                      */
/* ------------------------------------------------------------------ */
__global__ __launch_bounds__(256, 2)
void kattn(const float* __restrict__ x, float* __restrict__ out) {
    __shared__ __nv_bfloat16 KV[2][BN*SKH];   /* 18432 B, reused as scratch */

    const int tid  = threadIdx.x;
    const int lane = tid & 31;
    const int wid  = tid >> 5;
    const int wr   = wid & 3;       /* row block   */
    const int hN   = wid >> 2;      /* column half */
    const int b    = blockIdx.y;
    const int n0   = blockIdx.x * BM;
    const int grp  = lane >> 3;
    const int gi   = lane & 7;
    const __nv_bfloat16* tok = g_tok + (size_t)b*NPIX*CCH;

    const unsigned kv0 = (unsigned)__cvta_generic_to_shared(&KV[0][0]);

    /* all-ones bf16 B fragment for row-sum MMAs */
    unsigned ones2[2];
    ones2[0] = 0x3F803F80u;
    ones2[1] = 0x3F803F80u;

    /* Q fragments from the pre-scaled token array */
    unsigned qa[4][4];
    {
        const __nv_bfloat16* tq = g_tokq + (size_t)b*NPIX*CCH;
        int g0 = n0 + wr*16 + (lane >> 2);
        int kk = (lane & 3)*2;
        const __nv_bfloat16* q0 = tq + (size_t)g0*CCH;
        const __nv_bfloat16* q8 = tq + (size_t)(g0+8)*CCH;
        #pragma unroll
        for (int ks = 0; ks < 4; ks++) {
            qa[ks][0] = *reinterpret_cast<const unsigned*>(q0 + 16*ks + kk);
            qa[ks][1] = *reinterpret_cast<const unsigned*>(q8 + 16*ks + kk);
            qa[ks][2] = *reinterpret_cast<const unsigned*>(q0 + 16*ks + kk + 8);
            qa[ks][3] = *reinterpret_cast<const unsigned*>(q8 + 16*ks + kk + 8);
        }
    }

    float oc[8][4];   /* partial O over this warp's token half */
    #pragma unroll
    for (int i = 0; i < 8; i++) {
        #pragma unroll
        for (int j = 0; j < 4; j++) { oc[i][j] = 0.0f; }
    }
    float lacc[4];
    lacc[0] = 0.0f; lacc[1] = 0.0f; lacc[2] = 0.0f; lacc[3] = 0.0f;

    /* prefetch tile 0: 512 16B chunks, 256 threads x 2 */
    {
        #pragma unroll
        for (int u = 0; u < 2; u++) {
            int chunk = tid + u*256;
            int r  = chunk >> 3;
            int cg = (chunk & 7)*8;
            cpasync16(kv0 + (unsigned)(r*SKH + cg)*2u, tok + (size_t)r*CCH + cg);
        }
        asm volatile("cp.async.commit_group;" ::: "memory");
    }

    for (int t = 0; t < NITER; t++) {
        const int cur = t & 1;
        const unsigned kvb = kv0 + (unsigned)cur*(BN*SKH*2u);

        asm volatile("cp.async.wait_group 0;" ::: "memory");
        __syncthreads();

        if (t + 1 < NITER) {
            unsigned dst0 = kv0 + (unsigned)(cur ^ 1)*(BN*SKH*2u);
            #pragma unroll
            for (int u = 0; u < 2; u++) {
                int chunk = tid + u*256;
                int r  = chunk >> 3;
                int cg = (chunk & 7)*8;
                cpasync16(dst0 + (unsigned)(r*SKH + cg)*2u,
                          tok + (size_t)((t+1)*BN + r)*CCH + cg);
            }
            asm volatile("cp.async.commit_group;" ::: "memory");
        }

        /* GEMM1: sc = (Q*SC) * K^T over this warp's 32 columns */
        float sc[4][4];
        #pragma unroll
        for (int i = 0; i < 4; i++) {
            #pragma unroll
            for (int j = 0; j < 4; j++) { sc[i][j] = 0.0f; }
        }

        #pragma unroll
        for (int np = 0; np < 2; np++) {
            #pragma unroll
            for (int ks = 0; ks < 4; ks++) {
                int n_row = hN*32 + (2*np + (grp >> 1))*8 + gi;
                int k_off = 16*ks + (grp & 1)*8;
                unsigned r[4];
                ldsm4(r, kvb + (unsigned)(n_row*SKH + k_off)*2u);
                mma16816(sc[2*np+0], qa[ks], &r[0]);
                mma16816(sc[2*np+1], qa[ks], &r[2]);
            }
        }

        /* P = exp2(sc) */
        #pragma unroll
        for (int nt = 0; nt < 4; nt++) {
            sc[nt][0] = ex2f(sc[nt][0]);
            sc[nt][1] = ex2f(sc[nt][1]);
            sc[nt][2] = ex2f(sc[nt][2]);
            sc[nt][3] = ex2f(sc[nt][3]);
        }

        /* repack P C-frags (16x32) into 2 bf16 A k-groups */
        unsigned pa[2][4];
        #pragma unroll
        for (int j = 0; j < 2; j++) {
            pa[j][0] = packbf(sc[2*j+0][0], sc[2*j+0][1]);
            pa[j][1] = packbf(sc[2*j+0][2], sc[2*j+0][3]);
            pa[j][2] = packbf(sc[2*j+1][0], sc[2*j+1][1]);
            pa[j][3] = packbf(sc[2*j+1][2], sc[2*j+1][3]);
        }

        /* partial row sums via tensor core */
        #pragma unroll
        for (int j = 0; j < 2; j++) {
            mma16816(lacc, pa[j], ones2);
        }

        /* GEMM2: O += P * V over this warp's 32 token rows */
        #pragma unroll
        for (int np = 0; np < 4; np++) {
            #pragma unroll
            for (int ks = 0; ks < 2; ks++) {
                int tokr = hN*32 + 16*ks + (grp & 1)*8 + gi;
                int ch   = (2*np + (grp >> 1))*8;
                unsigned r[4];
                ldsm4t(r, kvb + (unsigned)(tokr*SKH + ch)*2u);
                mma16816(oc[2*np+0], pa[ks], &r[0]);
                mma16816(oc[2*np+1], pa[ks], &r[2]);
            }
        }
    }

    /* combine partner-warp partials (w and w+4) via smem scratch.     */
    /* KV buffer is done being read; reuse it: 4 blocks x 32 lanes x   */
    /* 36 floats = 18432 B exactly.                                    */
    float* scratch = reinterpret_cast<float*>(&KV[0][0]);
    __syncthreads();
    if (wid >= 4) {
        float* s = scratch + (wr*32 + lane)*36;
        #pragma unroll
        for (int nt = 0; nt < 8; nt++) {
            #pragma unroll
            for (int j = 0; j < 4; j++) { s[nt*4 + j] = oc[nt][j]; }
        }
        s[32] = lacc[0];
        s[33] = lacc[2];
    }
    __syncthreads();
    if (wid < 4) {
        float* s = scratch + (wr*32 + lane)*36;
        #pragma unroll
        for (int nt = 0; nt < 8; nt++) {
            #pragma unroll
            for (int j = 0; j < 4; j++) { oc[nt][j] += s[nt*4 + j]; }
        }
        float inv0 = 1.0f / (lacc[0] + s[32]);
        float inv1 = 1.0f / (lacc[2] + s[33]);

        int r0g = n0 + wr*16 + (lane >> 2);
        #pragma unroll
        for (int nt = 0; nt < 8; nt++) {
            int ch = nt*8 + (lane & 3)*2;
            #pragma unroll
            for (int dv = 0; dv < 2; dv++) {
                size_t idx0 = ((size_t)b*CCH + ch + dv)*NPIX + r0g;
                out[idx0]     = x[idx0]     + 0.2f*oc[nt][dv]*inv0;
                out[idx0 + 8] = x[idx0 + 8] + 0.2f*oc[nt][2+dv]*inv1;
            }
        }
    }
}

/* ------------------------------------------------------------------ */
extern "C" void kernel_launch(void* const* d_in, const int* in_sizes, int n_in,
                              void* d_out, int out_size) {
    const float* x      = (const float*)d_in[0];
    const float* w_red  = (const float*)d_in[1];
    const float* b_red  = (const float*)d_in[2];
    const float* w_dil  = (const float*)d_in[3];
    const float* b_dil  = (const float*)d_in[4];
    const float* w_fuse = (const float*)d_in[5];
    const float* b_fuse = (const float*)d_in[6];
    float* out = (float*)d_out;

    int npx = BATCH*NPIX;
    kred<<<(npx+127)/128, 128>>>(x, w_red, b_red);
    kfuse<<<(npx+127)/128, 128>>>(w_dil, b_dil, w_fuse, b_fuse);

    dim3 grid(NPIX/BM, BATCH);
    kattn<<<grid, 256>>>(x, out);
}